// round 9
// baseline (speedup 1.0000x reference)
#include <cuda_runtime.h>
#include <cuda_bf16.h>
#include <cstdint>

#define B_ 2
#define S_ 2048
#define D_ 256
#define H_ 8

// Scratch (no allocations allowed -> static device globals)
__device__ float g_Q[(size_t)B_ * H_ * S_ * D_];   // tf32-rounded
__device__ float g_K[(size_t)B_ * H_ * S_ * D_];   // tf32-rounded
__device__ float g_V[(size_t)B_ * H_ * S_ * D_];   // tf32-rounded
__device__ float g_P[(size_t)B_ * H_ * S_ * S_];   // scores (raw) -> probs (tf32-rounded)
__device__ float g_O[(size_t)B_ * S_ * H_ * D_];   // raw fp32 [B,S,H,D]

// round-to-nearest tf32 (unbiased)
__device__ __forceinline__ float f2tf32(float x) {
    uint32_t r;
    asm("cvt.rna.tf32.f32 %0, %1;" : "=r"(r) : "f"(x));
    return __uint_as_float(r);
}

__device__ __forceinline__ void mma_tf32(float* c, const uint32_t* a, const uint32_t* b) {
    asm volatile(
        "mma.sync.aligned.m16n8k8.row.col.f32.tf32.tf32.f32 "
        "{%0,%1,%2,%3}, {%4,%5,%6,%7}, {%8,%9}, {%0,%1,%2,%3};"
        : "+f"(c[0]), "+f"(c[1]), "+f"(c[2]), "+f"(c[3])
        : "r"(a[0]), "r"(a[1]), "r"(a[2]), "r"(a[3]), "r"(b[0]), "r"(b[1]));
}

__device__ __forceinline__ void cpa16(uint32_t dst, const void* src) {
    asm volatile("cp.async.cg.shared.global [%0], [%1], 16;" :: "r"(dst), "l"(src));
}
__device__ __forceinline__ void cpa_commit() { asm volatile("cp.async.commit_group;"); }

#define SA_STRIDE 20     // 16 data + 4 pad floats: g*20+c bijective mod 32 banks
#define SBN_STRIDE 136   // 128 data + 8 pad: c*8+g bijective mod 32 banks
#define STAGES 4
#define STAGE_FLOATS 5120           // 2560 (A) + 2560 (B)
#define GEMM_SMEM_BYTES (STAGES * STAGE_FLOATS * 4)   // 80 KB

// ---------------------------------------------------------------------------
// 128x128 CTA tile tf32 tensor-core GEMM, 256 threads = 8 warps (2m x 4n),
// each warp 64x32 via m16n8k8. BK=16, 4-stage circular cp.async pipeline in
// dynamic smem, ONE barrier per stage, conflict-free padded strides.
// TB=false: C = A[M,K] * B[K,N] ; TB=true: C = A[M,K] * B[N,K]^T
// CVTL: round loads to tf32 (external fp32 inputs). CVTS: round stores.
// ---------------------------------------------------------------------------
template <bool TB, bool CVTL, bool CVTS>
__device__ __forceinline__ void gemm_cp(const float* __restrict__ A,
                                        const float* __restrict__ Bm,
                                        float* __restrict__ C,
                                        int K, int lda, int ldb, int ldc,
                                        float scale, int mtile)
{
    extern __shared__ float smem[];

    const int t    = threadIdx.x;
    const int lane = t & 31;
    const int wid  = t >> 5;
    const int wm   = wid >> 2;      // 0..1
    const int wn   = wid & 3;       // 0..3
    const int g    = lane >> 2;     // 0..7
    const int c    = lane & 3;      // 0..3
    const int m0   = mtile * 128;
    const int n0   = blockIdx.y * 128;

    const uint32_t sbase = (uint32_t)__cvta_generic_to_shared(smem);

    // loader indices: 2 x 16B chunks for A, 2 for B
    const int aRow0 = t >> 2,         aC0 = (t & 3) * 4;
    const int aRow1 = (t + 256) >> 2, aC1 = aC0;
    const int bK0 = t >> 5,           bN0 = (t & 31) * 4;
    const int bK1 = (t + 256) >> 5,   bN1 = bN0;

    // issue one BK=16 stage into circular buffer s; ALWAYS commit (uniform
    // group accounting so wait_group 2 retires exactly stage ks, incl. tail)
    auto issue_stage = [&](int k0, int s, bool pred) {
        if (pred) {
            const uint32_t sa = sbase + (uint32_t)(s * STAGE_FLOATS) * 4u;
            const uint32_t sb = sa + 2560u * 4u;
            cpa16(sa + (aRow0 * SA_STRIDE + aC0) * 4, A + (size_t)(m0 + aRow0) * lda + k0 + aC0);
            cpa16(sa + (aRow1 * SA_STRIDE + aC1) * 4, A + (size_t)(m0 + aRow1) * lda + k0 + aC1);
            if (TB) {
                cpa16(sb + (aRow0 * SA_STRIDE + aC0) * 4, Bm + (size_t)(n0 + aRow0) * ldb + k0 + aC0);
                cpa16(sb + (aRow1 * SA_STRIDE + aC1) * 4, Bm + (size_t)(n0 + aRow1) * ldb + k0 + aC1);
            } else {
                cpa16(sb + (bK0 * SBN_STRIDE + bN0) * 4, Bm + (size_t)(k0 + bK0) * ldb + n0 + bN0);
                cpa16(sb + (bK1 * SBN_STRIDE + bN1) * 4, Bm + (size_t)(k0 + bK1) * ldb + n0 + bN1);
            }
        }
        cpa_commit();
    };

    float acc[4][4][4] = {};

    auto ldval = [&](const float* p) -> uint32_t {
        float v = *p;
        if (CVTL) v = f2tf32(v);
        return __float_as_uint(v);
    };

    auto compute_stage = [&](int s) {
        const float* as = smem + s * STAGE_FLOATS;
        const float* bs = as + 2560;
        #pragma unroll
        for (int kt = 0; kt < 2; kt++) {
            uint32_t a[4][4], b[4][2];
            #pragma unroll
            for (int i = 0; i < 4; i++) {
                const int row = wm * 64 + i * 16 + g;
                const int base = row * SA_STRIDE + kt * 8 + c;
                a[i][0] = ldval(as + base);
                a[i][1] = ldval(as + base + 8 * SA_STRIDE);
                a[i][2] = ldval(as + base + 4);
                a[i][3] = ldval(as + base + 8 * SA_STRIDE + 4);
            }
            #pragma unroll
            for (int j = 0; j < 4; j++) {
                if (TB) {
                    const int base = (wn * 32 + j * 8 + g) * SA_STRIDE + kt * 8 + c;
                    b[j][0] = ldval(bs + base);
                    b[j][1] = ldval(bs + base + 4);
                } else {
                    const int base = (kt * 8 + c) * SBN_STRIDE + wn * 32 + j * 8 + g;
                    b[j][0] = ldval(bs + base);
                    b[j][1] = ldval(bs + base + 4 * SBN_STRIDE);
                }
            }
            #pragma unroll
            for (int i = 0; i < 4; i++)
                #pragma unroll
                for (int j = 0; j < 4; j++)
                    mma_tf32(acc[i][j], a[i], b[j]);
        }
    };

    const int KS = K >> 4;
    // prologue: stages 0,1,2 (predicated; commits always happen)
    issue_stage(0,  0, true);
    issue_stage(16, 1, 1 < KS);
    issue_stage(32, 2, 2 < KS);

    for (int ks = 0; ks < KS; ks++) {
        // groups committed so far: ks+3 (indices 0..ks+2); keep <=2 younger
        // outstanding -> group ks (stage ks) is complete.
        asm volatile("cp.async.wait_group 2;");
        __syncthreads();
        // overwrites buffer (ks-1)%4: all threads finished computing it
        // before the barrier above.
        issue_stage((ks + 3) << 4, (ks + 3) & 3, ks + 3 < KS);
        compute_stage(ks & 3);
    }

    // Epilogue: m16n8 c-frag -> (g,2c),(g,2c+1) and (g+8,...)
    #pragma unroll
    for (int i = 0; i < 4; i++) {
        #pragma unroll
        for (int j = 0; j < 4; j++) {
            const int row = m0 + wm * 64 + i * 16 + g;
            const int col = n0 + wn * 32 + j * 8 + c * 2;
            float2 lo = {acc[i][j][0] * scale, acc[i][j][1] * scale};
            float2 hi = {acc[i][j][2] * scale, acc[i][j][3] * scale};
            if (CVTS) {
                lo.x = f2tf32(lo.x); lo.y = f2tf32(lo.y);
                hi.x = f2tf32(hi.x); hi.y = f2tf32(hi.y);
            }
            *(float2*)(C + (size_t)row * ldc + col)       = lo;
            *(float2*)(C + (size_t)(row + 8) * ldc + col) = hi;
        }
    }
}

// ---------------------------------------------------------------------------
// 1) Q/K/V projections (external fp32 in -> tf32-rounded out)
// ---------------------------------------------------------------------------
__global__ __launch_bounds__(256, 2) void proj_kernel(const float* __restrict__ x,
                                                      const float* __restrict__ wQ,
                                                      const float* __restrict__ wK,
                                                      const float* __restrict__ wV)
{
    const int z     = blockIdx.z;
    const int which = z / (B_ * H_);
    const int bh    = z % (B_ * H_);
    const int b     = bh / H_;
    const int h     = bh % H_;

    const float* A = x + (size_t)b * S_ * D_;
    const float* W = (which == 0 ? wQ : which == 1 ? wK : wV) + (size_t)h * D_ * D_;
    float* C = (which == 0 ? g_Q : which == 1 ? g_K : g_V) + (size_t)bh * S_ * D_;

    gemm_cp<false, true, true>(A, W, C, D_, D_, D_, D_, 1.0f, blockIdx.x);
}

// ---------------------------------------------------------------------------
// 2) Scores = Q @ K^T / sqrt(D); inputs pre-rounded, raw fp32 scores out
// ---------------------------------------------------------------------------
__global__ __launch_bounds__(256, 2) void qk_kernel()
{
    if (blockIdx.y > blockIdx.x) return;
    const int bh = blockIdx.z;
    const float* A  = g_Q + (size_t)bh * S_ * D_;
    const float* Bm = g_K + (size_t)bh * S_ * D_;
    float* C = g_P + (size_t)bh * S_ * S_;
    gemm_cp<true, false, false>(A, Bm, C, D_, D_, D_, S_, 0.0625f, blockIdx.x);
}

// ---------------------------------------------------------------------------
// 3) Causal softmax; writes tf32-rounded probs, zero-fills j>i
// ---------------------------------------------------------------------------
__global__ void softmax_kernel()
{
    const int i  = blockIdx.x;
    const int bh = blockIdx.y;
    float* row = g_P + ((size_t)bh * S_ + i) * S_;
    const int len = i + 1;
    const int t = threadIdx.x;
    __shared__ float red[8];

    float m = -3.402823e38f;
    for (int j = t; j < len; j += 256) m = fmaxf(m, row[j]);
    #pragma unroll
    for (int o = 16; o; o >>= 1) m = fmaxf(m, __shfl_xor_sync(0xffffffffu, m, o));
    if ((t & 31) == 0) red[t >> 5] = m;
    __syncthreads();
    m = red[0];
    #pragma unroll
    for (int w = 1; w < 8; w++) m = fmaxf(m, red[w]);
    __syncthreads();

    float s = 0.0f;
    for (int j = t; j < len; j += 256) {
        float e = __expf(row[j] - m);
        row[j] = e;
        s += e;
    }
    #pragma unroll
    for (int o = 16; o; o >>= 1) s += __shfl_xor_sync(0xffffffffu, s, o);
    if ((t & 31) == 0) red[t >> 5] = s;
    __syncthreads();
    float tot = red[0];
    #pragma unroll
    for (int w = 1; w < 8; w++) tot += red[w];
    const float inv = 1.0f / tot;

    for (int j = t; j < len; j += 256) row[j] = f2tf32(row[j] * inv);
    for (int j = len + t; j < S_; j += 256) row[j] = 0.0f;
}

// ---------------------------------------------------------------------------
// 4) O = P @ V, K truncated at causal boundary; heavy tiles first
// ---------------------------------------------------------------------------
__global__ __launch_bounds__(256, 2) void pv_kernel()
{
    const int bh = blockIdx.z;
    const int b  = bh / H_;
    const int h  = bh % H_;
    const int mtile = gridDim.x - 1 - blockIdx.x;
    const int Keff = (mtile + 1) * 128;
    const float* A  = g_P + (size_t)bh * S_ * S_;
    const float* Bm = g_V + (size_t)bh * S_ * D_;
    float* C = g_O + (size_t)b * S_ * H_ * D_ + (size_t)h * D_;
    gemm_cp<false, false, false>(A, Bm, C, Keff, S_, D_, H_ * D_, 1.0f, mtile);
}

// ---------------------------------------------------------------------------
// 5) out[B*S, D] = g_O[B*S, H*D] @ wO[H*D, D]  (raw fp32 inputs -> cvt on load)
// ---------------------------------------------------------------------------
__global__ __launch_bounds__(256, 2) void out_kernel(const float* __restrict__ wO,
                                                     float* __restrict__ out)
{
    gemm_cp<false, true, false>(g_O, wO, out, H_ * D_, H_ * D_, D_, D_, 1.0f, blockIdx.x);
}

// ---------------------------------------------------------------------------
extern "C" void kernel_launch(void* const* d_in, const int* in_sizes, int n_in,
                              void* d_out, int out_size)
{
    const float* x  = (const float*)d_in[0];
    // d_in[1] = timestamp (dead code in reference)
    const float* wQ = (const float*)d_in[2];
    const float* wK = (const float*)d_in[3];
    const float* wV = (const float*)d_in[4];
    const float* wO = (const float*)d_in[5];
    // d_in[6] = theta (dead code)
    float* out = (float*)d_out;

    // host-side attribute set (idempotent; not a graph node)
    cudaFuncSetAttribute(proj_kernel, cudaFuncAttributeMaxDynamicSharedMemorySize, GEMM_SMEM_BYTES);
    cudaFuncSetAttribute(qk_kernel,   cudaFuncAttributeMaxDynamicSharedMemorySize, GEMM_SMEM_BYTES);
    cudaFuncSetAttribute(pv_kernel,   cudaFuncAttributeMaxDynamicSharedMemorySize, GEMM_SMEM_BYTES);
    cudaFuncSetAttribute(out_kernel,  cudaFuncAttributeMaxDynamicSharedMemorySize, GEMM_SMEM_BYTES);

    dim3 blk(256);
    proj_kernel<<<dim3(S_ / 128, D_ / 128, 3 * B_ * H_), blk, GEMM_SMEM_BYTES>>>(x, wQ, wK, wV);
    qk_kernel<<<dim3(S_ / 128, S_ / 128, B_ * H_), blk, GEMM_SMEM_BYTES>>>();
    softmax_kernel<<<dim3(S_, B_ * H_), blk>>>();
    pv_kernel<<<dim3(S_ / 128, D_ / 128, B_ * H_), blk, GEMM_SMEM_BYTES>>>();
    out_kernel<<<dim3(B_ * S_ / 128, D_ / 128, 1), blk, GEMM_SMEM_BYTES>>>(wO, out);
}

// round 12
// speedup vs baseline: 1.4029x; 1.4029x over previous
#include <cuda_runtime.h>
#include <cuda_fp16.h>
#include <cstdint>

#define B_ 2
#define S_ 2048
#define D_ 256
#define H_ 8
#define BHN (B_ * H_)

// Scratch (static device globals; no allocations)
__device__ __half g_Xh[(size_t)B_ * S_ * D_];          // x, fp16
__device__ __half g_Wt[(size_t)3 * H_ * D_ * D_];      // W^T per head, fp16 [which][h][e][d]
__device__ __half g_WOt[(size_t)D_ * H_ * D_];         // wO^T fp16 [256][2048]
__device__ __half g_Q[(size_t)BHN * S_ * D_];          // fp16
__device__ __half g_K[(size_t)BHN * S_ * D_];
__device__ __half g_V[(size_t)BHN * S_ * D_];
__device__ __half g_Vt[(size_t)BHN * D_ * S_];         // V^T fp16 [e][s]
__device__ float  g_P[(size_t)BHN * S_ * S_];          // fp32 scores
__device__ __half g_Ph[(size_t)BHN * S_ * S_];         // fp16 probs
__device__ __half g_Oh[(size_t)B_ * S_ * H_ * D_];     // fp16 attention out [B,S,H*D]

__device__ __forceinline__ void cpa16(uint32_t dst, const void* src) {
    asm volatile("cp.async.cg.shared.global [%0], [%1], 16;" :: "r"(dst), "l"(src));
}

__device__ __forceinline__ void mma_h(float* c, const uint32_t* a, const uint32_t* b) {
    asm volatile(
        "mma.sync.aligned.m16n8k16.row.col.f32.f16.f16.f32 "
        "{%0,%1,%2,%3}, {%4,%5,%6,%7}, {%8,%9}, {%0,%1,%2,%3};"
        : "+f"(c[0]), "+f"(c[1]), "+f"(c[2]), "+f"(c[3])
        : "r"(a[0]), "r"(a[1]), "r"(a[2]), "r"(a[3]), "r"(b[0]), "r"(b[1]));
}

#define STAGE_B 20480u              // A: 128 rows * 80B + B: 128 rows * 80B
#define HP_SMEM (4 * 20480)         // 80 KB, 4-stage ring (2 CTAs/SM: 160KB < 228KB)

// ---------------------------------------------------------------------------
// fp16 NT tensor-core GEMM: C[128x128](+m0,n0) = A[M,K] * B[N,K]^T, both
// k-major fp16. BK=32 halfs (64B data rows padded to 80B: half2-addr =
// row*20 + k2, banks (20g+c) bijective mod 32 -> conflict-free frag loads).
// 256 threads = 8 warps (2m x 4n), warp 64x32 via m16n8k16. 4-stage cp.async
// ring, one barrier per stage (R8-proven schedule). OUTM: 0=fp32 C, 1=half C.
// ---------------------------------------------------------------------------
template <int OUTM>
__device__ __forceinline__ void gemm_h(const __half* __restrict__ A,
                                       const __half* __restrict__ Bm,
                                       void* __restrict__ Cv,
                                       int K, int lda, int ldb, int ldc,
                                       float scale, int m0, int n0)
{
    extern __shared__ float dsm[];
    uint32_t* s32 = (uint32_t*)dsm;

    const int t    = threadIdx.x;
    const int lane = t & 31;
    const int wid  = t >> 5;
    const int wm   = wid >> 2;      // 0..1
    const int wn   = wid & 3;       // 0..3
    const int g    = lane >> 2;     // 0..7
    const int c    = lane & 3;      // 0..3

    const uint32_t sbase = (uint32_t)__cvta_generic_to_shared(dsm);

    // loader: 512 16B chunks per operand tile; thread handles 2 per operand
    const int r0 = t >> 2,         u0 = (t & 3);
    const int r1 = (t + 256) >> 2, u1 = u0;

    auto issue = [&](int kc, int s, bool pred) {
        if (pred) {
            const uint32_t sa = sbase + (uint32_t)s * STAGE_B;
            const uint32_t sb = sa + 10240u;
            cpa16(sa + (uint32_t)(r0 * 80 + u0 * 16), A + (size_t)(m0 + r0) * lda + kc + u0 * 8);
            cpa16(sa + (uint32_t)(r1 * 80 + u1 * 16), A + (size_t)(m0 + r1) * lda + kc + u1 * 8);
            cpa16(sb + (uint32_t)(r0 * 80 + u0 * 16), Bm + (size_t)(n0 + r0) * ldb + kc + u0 * 8);
            cpa16(sb + (uint32_t)(r1 * 80 + u1 * 16), Bm + (size_t)(n0 + r1) * ldb + kc + u1 * 8);
        }
        asm volatile("cp.async.commit_group;");
    };

    float acc[4][4][4] = {};   // [m-atom][n-atom][frag]

    auto compute = [&](int s) {
        const uint32_t* as = s32 + (size_t)s * (STAGE_B / 4);
        const uint32_t* bs = as + 2560;
        #pragma unroll
        for (int kt = 0; kt < 2; kt++) {
            uint32_t a[4][4], b[4][2];
            #pragma unroll
            for (int i = 0; i < 4; i++) {
                const int base = (wm * 64 + i * 16 + g) * 20 + kt * 8 + c;
                a[i][0] = as[base];          // (row,   k0..1)
                a[i][1] = as[base + 160];    // (row+8, k0..1)
                a[i][2] = as[base + 4];      // (row,   k8..9)
                a[i][3] = as[base + 164];    // (row+8, k8..9)
            }
            #pragma unroll
            for (int j = 0; j < 4; j++) {
                const int base = (wn * 32 + j * 8 + g) * 20 + kt * 8 + c;
                b[j][0] = bs[base];          // (n, k0..1)
                b[j][1] = bs[base + 4];      // (n, k8..9)
            }
            #pragma unroll
            for (int i = 0; i < 4; i++)
                #pragma unroll
                for (int j = 0; j < 4; j++)
                    mma_h(acc[i][j], a[i], b[j]);
        }
    };

    const int KS = K >> 5;
    issue(0,  0, true);
    issue(32, 1, 1 < KS);
    issue(64, 2, 2 < KS);

    for (int ks = 0; ks < KS; ks++) {
        asm volatile("cp.async.wait_group 2;");   // retires exactly stage ks
        __syncthreads();                          // + proves compute(ks-1) done
        issue((ks + 3) << 5, (ks + 3) & 3, ks + 3 < KS);
        compute(ks & 3);
    }

    // epilogue: m16n8 cfrag -> (g,2c),(g,2c+1),(g+8,..)
    #pragma unroll
    for (int i = 0; i < 4; i++) {
        #pragma unroll
        for (int j = 0; j < 4; j++) {
            const int row = m0 + wm * 64 + i * 16 + g;
            const int col = n0 + wn * 32 + j * 8 + 2 * c;
            if (OUTM == 0) {
                float* C = (float*)Cv;
                float2 lo = {acc[i][j][0] * scale, acc[i][j][1] * scale};
                float2 hi = {acc[i][j][2] * scale, acc[i][j][3] * scale};
                *(float2*)(C + (size_t)row * ldc + col)       = lo;
                *(float2*)(C + (size_t)(row + 8) * ldc + col) = hi;
            } else {
                __half* C = (__half*)Cv;
                __half2 lo = __floats2half2_rn(acc[i][j][0] * scale, acc[i][j][1] * scale);
                __half2 hi = __floats2half2_rn(acc[i][j][2] * scale, acc[i][j][3] * scale);
                *(__half2*)(C + (size_t)row * ldc + col)       = lo;
                *(__half2*)(C + (size_t)(row + 8) * ldc + col) = hi;
            }
        }
    }
}

// ---------------- GEMM wrappers (all NT) ----------------
__global__ __launch_bounds__(256, 2) void hp_proj() {
    const int z = blockIdx.z, which = z / BHN, bh = z % BHN, b = bh / H_, h = bh % H_;
    const __half* A  = g_Xh + (size_t)b * S_ * D_;
    const __half* Bm = g_Wt + ((size_t)which * H_ + h) * D_ * D_;
    __half* C = (which == 0 ? g_Q : which == 1 ? g_K : g_V) + (size_t)bh * S_ * D_;
    gemm_h<1>(A, Bm, C, D_, D_, D_, D_, 1.0f, blockIdx.x * 128, blockIdx.y * 128);
}
__global__ __launch_bounds__(256, 2) void hp_qk() {
    if (blockIdx.y > blockIdx.x) return;   // fully above causal diagonal
    const int bh = blockIdx.z;
    gemm_h<0>(g_Q + (size_t)bh * S_ * D_, g_K + (size_t)bh * S_ * D_,
              g_P + (size_t)bh * S_ * S_, D_, D_, D_, S_,
              0.0625f, blockIdx.x * 128, blockIdx.y * 128);
}
__global__ __launch_bounds__(256, 2) void hp_pv() {
    const int bh = blockIdx.z, b = bh / H_, h = bh % H_;
    const int mtile = (int)gridDim.x - 1 - (int)blockIdx.x;   // heavy tiles first
    const int Keff = (mtile + 1) * 128;
    __half* C = g_Oh + (size_t)b * S_ * (H_ * D_) + h * D_;
    gemm_h<1>(g_Ph + (size_t)bh * S_ * S_, g_Vt + (size_t)bh * D_ * S_,
              C, Keff, S_, S_, H_ * D_, 1.0f, mtile * 128, blockIdx.y * 128);
}
__global__ __launch_bounds__(256, 2) void hp_out(float* __restrict__ out) {
    gemm_h<0>(g_Oh, g_WOt, out, H_ * D_, H_ * D_, H_ * D_, D_,
              1.0f, blockIdx.x * 128, blockIdx.y * 128);
}

// ---------------- prep kernels ----------------
__global__ void h_copy(const float* __restrict__ in, __half* __restrict__ out, int n) {
    int i = blockIdx.x * blockDim.x + threadIdx.x;
    if (i < n) out[i] = __float2half_rn(in[i]);
}
// fp32 [R][C] -> fp16 [C][R] (per z-slice)
__global__ void tr_f2h(const float* __restrict__ in, __half* __restrict__ out, int R, int C) {
    __shared__ float sm[32][33];
    const int r0 = blockIdx.x * 32, c0 = blockIdx.y * 32;
    const float* ip = in + (size_t)blockIdx.z * R * C;
    __half* op = out + (size_t)blockIdx.z * R * C;
    for (int j = threadIdx.y; j < 32; j += 8)
        sm[j][threadIdx.x] = ip[(size_t)(r0 + j) * C + c0 + threadIdx.x];
    __syncthreads();
    for (int j = threadIdx.y; j < 32; j += 8)
        op[(size_t)(c0 + j) * R + r0 + threadIdx.x] = __float2half_rn(sm[threadIdx.x][j]);
}
// fp16 [R][C] -> fp16 [C][R] (per z-slice); h->f->h round-trip is exact
__global__ void tr_h2h(const __half* __restrict__ in, __half* __restrict__ out, int R, int C) {
    __shared__ float sm[32][33];
    const int r0 = blockIdx.x * 32, c0 = blockIdx.y * 32;
    const __half* ip = in + (size_t)blockIdx.z * R * C;
    __half* op = out + (size_t)blockIdx.z * R * C;
    for (int j = threadIdx.y; j < 32; j += 8)
        sm[j][threadIdx.x] = __half2float(ip[(size_t)(r0 + j) * C + c0 + threadIdx.x]);
    __syncthreads();
    for (int j = threadIdx.y; j < 32; j += 8)
        op[(size_t)(c0 + j) * R + r0 + threadIdx.x] = __float2half_rn(sm[threadIdx.x][j]);
}

// ---------------- causal softmax: fp32 scores in, fp16 probs out ----------------
__global__ void softmax_kernel() {
    const int i = blockIdx.x, bh = blockIdx.y;
    const float* row = g_P + ((size_t)bh * S_ + i) * S_;
    __half* orow = g_Ph + ((size_t)bh * S_ + i) * S_;
    const int len = i + 1, t = threadIdx.x;
    __shared__ float red[8];

    float m = -3.402823e38f;
    for (int j = t; j < len; j += 256) m = fmaxf(m, row[j]);
    #pragma unroll
    for (int o = 16; o; o >>= 1) m = fmaxf(m, __shfl_xor_sync(0xffffffffu, m, o));
    if ((t & 31) == 0) red[t >> 5] = m;
    __syncthreads();
    m = red[0];
    #pragma unroll
    for (int w = 1; w < 8; w++) m = fmaxf(m, red[w]);
    __syncthreads();

    float s = 0.0f;
    for (int j = t; j < len; j += 256) s += __expf(row[j] - m);
    #pragma unroll
    for (int o = 16; o; o >>= 1) s += __shfl_xor_sync(0xffffffffu, s, o);
    if ((t & 31) == 0) red[t >> 5] = s;
    __syncthreads();
    float tot = red[0];
    #pragma unroll
    for (int w = 1; w < 8; w++) tot += red[w];
    const float inv = 1.0f / tot;

    for (int j = t; j < len; j += 256)
        orow[j] = __float2half_rn(__expf(row[j] - m) * inv);
    for (int j = len + t; j < S_; j += 256) orow[j] = __float2half_rn(0.0f);
}

// ---------------------------------------------------------------------------
extern "C" void kernel_launch(void* const* d_in, const int* in_sizes, int n_in,
                              void* d_out, int out_size)
{
    const float* x  = (const float*)d_in[0];
    // d_in[1] = timestamp (dead code in reference)
    const float* wQ = (const float*)d_in[2];
    const float* wK = (const float*)d_in[3];
    const float* wV = (const float*)d_in[4];
    const float* wO = (const float*)d_in[5];
    // d_in[6] = theta (dead code)
    float* out = (float*)d_out;

    cudaFuncSetAttribute(hp_proj, cudaFuncAttributeMaxDynamicSharedMemorySize, HP_SMEM);
    cudaFuncSetAttribute(hp_qk,   cudaFuncAttributeMaxDynamicSharedMemorySize, HP_SMEM);
    cudaFuncSetAttribute(hp_pv,   cudaFuncAttributeMaxDynamicSharedMemorySize, HP_SMEM);
    cudaFuncSetAttribute(hp_out,  cudaFuncAttributeMaxDynamicSharedMemorySize, HP_SMEM);

    __half* xh;  cudaGetSymbolAddress((void**)&xh,  g_Xh);
    __half* wt;  cudaGetSymbolAddress((void**)&wt,  g_Wt);
    __half* wot; cudaGetSymbolAddress((void**)&wot, g_WOt);
    __half* vs;  cudaGetSymbolAddress((void**)&vs,  g_V);
    __half* vt;  cudaGetSymbolAddress((void**)&vt,  g_Vt);

    dim3 tb(32, 8);
    h_copy<<<(B_ * S_ * D_ + 511) / 512, 512>>>(x, xh, B_ * S_ * D_);
    tr_f2h<<<dim3(8, 8, H_), tb>>>(wQ, wt,                      D_, D_);
    tr_f2h<<<dim3(8, 8, H_), tb>>>(wK, wt + H_ * D_ * D_,       D_, D_);
    tr_f2h<<<dim3(8, 8, H_), tb>>>(wV, wt + 2 * H_ * D_ * D_,   D_, D_);
    tr_f2h<<<dim3(64, 8, 1), tb>>>(wO, wot, H_ * D_, D_);

    dim3 blk(256);
    hp_proj<<<dim3(S_ / 128, D_ / 128, 3 * BHN), blk, HP_SMEM>>>();
    tr_h2h<<<dim3(64, 8, BHN), tb>>>(vs, vt, S_, D_);
    hp_qk<<<dim3(S_ / 128, S_ / 128, BHN), blk, HP_SMEM>>>();
    softmax_kernel<<<dim3(S_, BHN), blk>>>();
    hp_pv<<<dim3(S_ / 128, D_ / 128, BHN), blk, HP_SMEM>>>();
    hp_out<<<dim3(B_ * S_ / 128, D_ / 128, 1), blk, HP_SMEM>>>(out);
}